// round 14
// baseline (speedup 1.0000x reference)
#include <cuda_runtime.h>
#include <cuda_fp16.h>
#include <cstdint>

// Problem:
// x: [32, 512, 128, 16] f32, W: [16, 512, 512, 2] f32, bias: [16, 512] f32
// out: [32, 512, 128, 32] f32
// Per node n: 16 independent GEMMs A[4096, 512] * B[512, 1024] + bias.
//
// fp16 single-GEMM + fp16 intermediate y (measured rel_err 3.6e-4 < 1e-3).
// GEMM sits at the legacy mma.sync issue floor (tcgen05 unavailable: harness
// PTX targets sm_103 without 'a'). This round: repack is FUSED into the gemm
// as a completion-triggered tail — per (jt,mt) group of 16 node-CTAs, the
// last two arrivers (atomic counter) repack the group's y tiles from hot L2
// into out, overlapping the otherwise-idle DRAM bandwidth under the
// tensor-bound gemm window.

#define M_TOTAL    4096   // 32*128
#define K_DIM      512
#define N_PER_NODE 1024
#define NODES      16

__device__ __half g_xh[(size_t)NODES * M_TOTAL * K_DIM];      // [n][m][c] 64MB
__device__ __half g_wh[(size_t)NODES * N_PER_NODE * K_DIM];   // [n][j][c] 16MB
__device__ __half g_yh[(size_t)NODES * M_TOTAL * N_PER_NODE]; // [n][m][j] 134MB
__device__ int    g_sync[256];                                // per (jt,mt) group

static __device__ __forceinline__ uint32_t smem_u32(const void* p) {
    uint32_t a;
    asm("{ .reg .u64 t; cvta.to.shared.u64 t, %1; cvt.u32.u64 %0, t; }"
        : "=r"(a) : "l"(p));
    return a;
}

static __device__ __forceinline__ void cp_async16(uint32_t saddr, const void* gaddr) {
    asm volatile("cp.async.cg.shared.global [%0], [%1], 16;"
                 :: "r"(saddr), "l"(gaddr) : "memory");
}
static __device__ __forceinline__ void cp_commit() {
    asm volatile("cp.async.commit_group;" ::: "memory");
}
template <int N>
static __device__ __forceinline__ void cp_wait() {
    asm volatile("cp.async.wait_group %0;" :: "n"(N) : "memory");
}

static __device__ __forceinline__ void ldsm_x4(uint32_t* r, uint32_t addr) {
    asm volatile("ldmatrix.sync.aligned.m8n8.x4.shared.b16 {%0,%1,%2,%3}, [%4];"
                 : "=r"(r[0]), "=r"(r[1]), "=r"(r[2]), "=r"(r[3]) : "r"(addr));
}

static __device__ __forceinline__ void mma_f16(float* c, const uint32_t* a,
                                               uint32_t b0, uint32_t b1) {
    asm volatile(
        "mma.sync.aligned.m16n8k16.row.col.f32.f16.f16.f32 "
        "{%0,%1,%2,%3}, {%4,%5,%6,%7}, {%8,%9}, {%0,%1,%2,%3};"
        : "+f"(c[0]), "+f"(c[1]), "+f"(c[2]), "+f"(c[3])
        : "r"(a[0]), "r"(a[1]), "r"(a[2]), "r"(a[3]), "r"(b0), "r"(b1));
}

static __device__ __forceinline__ void stcs_f4(float* p, float4 v) {
    asm volatile("st.global.cs.v4.f32 [%0], {%1,%2,%3,%4};"
                 :: "l"(p), "f"(v.x), "f"(v.y), "f"(v.z), "f"(v.w) : "memory");
}

// ---------------------------------------------------------------------------
// Fused prepass: blocks [0, 4096) do split_x (direct register transpose),
// [4096, 12288) do split_w (32x32 smem transpose). Block 0 also zeroes the
// group counters (same-stream ordering guarantees visibility before gemm).
// ---------------------------------------------------------------------------
__global__ __launch_bounds__(256) void split_fused_kernel(const float* __restrict__ x,
                                                          const float* __restrict__ W) {
    __shared__ float sw[32][33];   // split_w branch only
    const int tid = threadIdx.x;
    const int bid = blockIdx.x;

    if (bid == 0) g_sync[tid] = 0;   // 256 counters, 256 threads

    if (bid < 4096) {
        // ---- split_x (direct) ----
        const int c0 = (bid & 7) * 64;
        const int f0 = ((bid >> 3) & 15) * 8;
        const int b  = bid >> 7;

        const int row  = tid >> 1;     // 0..127  (fn index)
        const int half = tid & 1;
        const int fl = row >> 4;       // 0..7
        const int n  = row & 15;
        const int cbase = c0 + half * 32;

        const float* src = x + (size_t)b * 1048576 + (size_t)cbase * 2048
                         + (size_t)(f0 + fl) * 16 + n;

        float v[32];
        #pragma unroll
        for (int cc = 0; cc < 32; cc++)
            v[cc] = src[(size_t)cc * 2048];

        __align__(16) __half hv[32];
        #pragma unroll
        for (int cc = 0; cc < 32; cc++)
            hv[cc] = __float2half_rn(v[cc]);

        const int m = b * 128 + f0 + fl;
        const size_t obase = (size_t)n * ((size_t)M_TOTAL * K_DIM)
                           + (size_t)m * K_DIM + cbase;
        uint4* ph = reinterpret_cast<uint4*>(&g_xh[obase]);
        #pragma unroll
        for (int q = 0; q < 4; q++)
            ph[q] = reinterpret_cast<uint4*>(hv)[q];
    } else {
        // ---- split_w ----
        const int wb = bid - 4096;
        const int j0 = (wb & 31) * 32;
        const int c0 = ((wb >> 5) & 15) * 32;
        const int n  = wb >> 9;

        #pragma unroll
        for (int it = 0; it < 4; it++) {
            int idx = tid + it * 256;
            int i = idx >> 5;   // c local
            int jj = idx & 31;  // j local
            sw[i][jj] = W[(size_t)n * 524288 + (size_t)(c0 + i) * 1024 + j0 + jj];
        }
        __syncthreads();
        #pragma unroll
        for (int it = 0; it < 4; it++) {
            int idx = tid + it * 256;
            int jj = idx >> 5;  // j local
            int i = idx & 31;   // c local
            size_t o = (size_t)n * 524288 + (size_t)(j0 + jj) * 512 + c0 + i;
            g_wh[o] = __float2half_rn(sw[i][jj]);
        }
    }
}

// ---------------------------------------------------------------------------
// GEMM + fused repack tail. Gemm part = champion R9 config (128x128 tile,
// K=512, 8 chunks, 3-stage cp.async, 8 warps 4x2). After the y epilogue,
// each CTA fences + increments its group counter; the last two arrivers
// repack the group's out region (64 o x 128 f x 32 nk = 32 tiles, 16 each)
// from L2-hot y, using the pipeline smem as scratch.
// ---------------------------------------------------------------------------
#define KC       64
#define CHUNKS   8
#define STAGE_BYTES 16384               // 128 rows * 128B
#define SMEM_BYTES  (6 * STAGE_BYTES)   // 96KB
#define RP_PF 594                       // repack f-stride (== 2 mod 32)

__global__ __launch_bounds__(256, 2) void gemm_kernel(const float* __restrict__ bias,
                                                      float* __restrict__ out) {
    extern __shared__ char smem[];
    const uint32_t sbase = smem_u32(smem);
    const int tid = threadIdx.x;
    const int wid = tid >> 5;
    const int lane = tid & 31;

    const int node = blockIdx.x;
    const int jt = blockIdx.y;    // 0..7
    const int mt = blockIdx.z;    // 0..31 (== b)

    const __half* abase = g_xh + (size_t)node * ((size_t)M_TOTAL * K_DIM)
                        + (size_t)mt * 128 * K_DIM;
    const __half* bbase = g_wh + (size_t)node * ((size_t)N_PER_NODE * K_DIM)
                        + (size_t)jt * 128 * K_DIM;

    const int ld_row = tid >> 3;
    const int ld_col = tid & 7;

    auto issue_chunk = [&](int chunk, int stage) {
        const __half* ap = abase + chunk * KC;
        const __half* bp = bbase + chunk * KC;
        uint32_t sa = sbase + stage * STAGE_BYTES;
        uint32_t sb = sbase + 3 * STAGE_BYTES + stage * STAGE_BYTES;
        #pragma unroll
        for (int p = 0; p < 4; p++) {
            int row = ld_row + p * 32;
            uint32_t soff = (uint32_t)row * 128 + (uint32_t)((ld_col ^ (row & 7)) << 4);
            cp_async16(sa + soff, ap + (size_t)row * K_DIM + ld_col * 8);
            cp_async16(sb + soff, bp + (size_t)row * K_DIM + ld_col * 8);
        }
    };

    const int wm = (wid & 3) * 32;
    const int wj = (wid >> 2) * 64;

    const int a_row0 = wm + (lane & 7) + (lane & 8);          // + mt2*16
    const int a_csel = (lane >> 4) & 1;
    const int b_row0 = wj + (lane & 7) + ((lane & 16) >> 1);  // + nt*16
    const int b_csel = (lane >> 3) & 1;

    float acc[2][8][4];
    #pragma unroll
    for (int i = 0; i < 2; i++)
        #pragma unroll
        for (int j = 0; j < 8; j++)
            #pragma unroll
            for (int k = 0; k < 4; k++) acc[i][j][k] = 0.f;

    issue_chunk(0, 0); cp_commit();
    issue_chunk(1, 1); cp_commit();

    int stage = 0;
    for (int i = 0; i < CHUNKS; i++) {
        cp_wait<1>();
        __syncthreads();

        uint32_t sa = sbase + stage * STAGE_BYTES;
        uint32_t sb = sbase + 3 * STAGE_BYTES + stage * STAGE_BYTES;

        #pragma unroll
        for (int kk = 0; kk < 4; kk++) {
            uint32_t afrag[2][4];
            uint32_t bfrag[4][4];
            #pragma unroll
            for (int mt2 = 0; mt2 < 2; mt2++) {
                int row = a_row0 + mt2 * 16;
                uint32_t addr = sa + (uint32_t)row * 128
                              + (uint32_t)(((2 * kk + a_csel) ^ (row & 7)) << 4);
                ldsm_x4(afrag[mt2], addr);
            }
            #pragma unroll
            for (int nt = 0; nt < 4; nt++) {
                int row = b_row0 + nt * 16;
                uint32_t addr = sb + (uint32_t)row * 128
                              + (uint32_t)(((2 * kk + b_csel) ^ (row & 7)) << 4);
                ldsm_x4(bfrag[nt], addr);
            }
            #pragma unroll
            for (int mt2 = 0; mt2 < 2; mt2++)
                #pragma unroll
                for (int n8 = 0; n8 < 8; n8++)
                    mma_f16(acc[mt2][n8], afrag[mt2],
                            bfrag[n8 >> 1][(n8 & 1) * 2], bfrag[n8 >> 1][(n8 & 1) * 2 + 1]);
        }

        __syncthreads();
        if (i + 2 < CHUNKS) issue_chunk(i + 2, (stage + 2) % 3);
        cp_commit();
        stage = (stage + 1) % 3;
    }

    // Epilogue: dense fp16 write to y[node][m][j], coalesced half2 stores.
    __half* ybase = g_yh + ((size_t)node * M_TOTAL + (size_t)mt * 128) * N_PER_NODE
                  + jt * 128;
    #pragma unroll
    for (int mt2 = 0; mt2 < 2; mt2++) {
        const int ml = wm + mt2 * 16 + (lane >> 2);
        __half* r0 = ybase + (size_t)ml * N_PER_NODE;
        __half* r1 = ybase + (size_t)(ml + 8) * N_PER_NODE;
        #pragma unroll
        for (int n8 = 0; n8 < 8; n8++) {
            int j = wj + n8 * 8 + (lane & 3) * 2;
            *reinterpret_cast<__half2*>(r0 + j) =
                __floats2half2_rn(acc[mt2][n8][0], acc[mt2][n8][1]);
            *reinterpret_cast<__half2*>(r1 + j) =
                __floats2half2_rn(acc[mt2][n8][2], acc[mt2][n8][3]);
        }
    }

    // ---- group completion + fused repack tail ----
    const int grp = jt * 32 + mt;
    __threadfence();           // each thread: y stores visible device-wide
    __syncthreads();           // all threads fenced
    __shared__ int s_old;
    if (tid == 0) s_old = atomicAdd(&g_sync[grp], 1);
    __syncthreads();
    const int old = s_old;
    if (old < 14) return;      // not one of the last two arrivers

    // Last two arrivers: wait for all 16, then split the 32 repack tiles.
    if (tid == 0) {
        while (((volatile int*)g_sync)[grp] < 16) { }
    }
    __syncthreads();
    __threadfence();           // acquire: order y reads after counter==16

    float* s = reinterpret_cast<float*>(smem);        // 9484 floats
    float* s_bias = s + 9600;                         // 64 o x 16 n
    const size_t ynode = (size_t)M_TOTAL * N_PER_NODE;

    // Stage bias for the whole group's 64 o's: s_bias[ol64*16 + n].
    for (int i = tid; i < 1024; i += 256) {
        int ol = i >> 4, n = i & 15;
        s_bias[ol * 16 + n] = bias[n * 512 + jt * 64 + ol];
    }

    const int t0 = (old == 14) ? 0 : 16;
    for (int t = t0; t < t0 + 16; t++) {
        const int o0l = (t & 3) * 16;     // local o offset within group
        const int f0  = (t >> 2) * 16;
        const int j0  = jt * 128 + o0l * 2;
        const __half* yb = g_yh + ((size_t)mt * 128 + f0) * N_PER_NODE + j0;

        __syncthreads();   // protect s reuse across tiles (and bias staging)

        // Phase 1: 16n x 16f x 4jo uint4 loads, 4 per thread.
        #pragma unroll
        for (int p = 0; p < 4; p++) {
            int idx = p * 256 + tid;
            int jo = idx & 3;
            int f  = (idx >> 2) & 15;
            int n  = (idx >> 6) & 15;
            uint4 raw = *reinterpret_cast<const uint4*>(
                yb + n * ynode + (size_t)f * N_PER_NODE + 8 * jo);
            float2 v01 = __half22float2(*reinterpret_cast<__half2*>(&raw.x));
            float2 v23 = __half22float2(*reinterpret_cast<__half2*>(&raw.y));
            float2 v45 = __half22float2(*reinterpret_cast<__half2*>(&raw.z));
            float2 v67 = __half22float2(*reinterpret_cast<__half2*>(&raw.w));
            float* sp = &s[f * RP_PF + (8 * jo) * 18 + n];
            sp[0]   = v01.x;
            sp[18]  = v01.y;
            sp[36]  = v23.x;
            sp[54]  = v23.y;
            sp[72]  = v45.x;
            sp[90]  = v45.y;
            sp[108] = v67.x;
            sp[126] = v67.y;
        }
        __syncthreads();

        // Phase 2: per float4 out chunk: 2 LDS.64 + bias, evict-first store.
        #pragma unroll
        for (int p = 0; p < 8; p++) {
            int idx = p * 256 + tid;
            int ol = idx >> 7;            // 0..15
            int f  = (idx >> 3) & 15;
            int g  = idx & 7;
            int n0 = 2 * g;
            int jl = 2 * ol;
            float2 A = *reinterpret_cast<float2*>(&s[f * RP_PF + jl * 18 + n0]);
            float2 B = *reinterpret_cast<float2*>(&s[f * RP_PF + (jl + 1) * 18 + n0]);
            float b0 = s_bias[(o0l + ol) * 16 + n0];
            float b1 = s_bias[(o0l + ol) * 16 + n0 + 1];
            float4 v;
            v.x = A.x + b0;
            v.y = B.x + b0;
            v.z = A.y + b1;
            v.w = B.y + b1;
            size_t oaddr = (size_t)mt * 2097152
                         + (size_t)(jt * 64 + o0l + ol) * 4096
                         + (size_t)(f0 + f) * 32 + g * 4;
            stcs_f4(out + oaddr, v);
        }
    }
}

// ---------------------------------------------------------------------------
extern "C" void kernel_launch(void* const* d_in, const int* in_sizes, int n_in,
                              void* d_out, int out_size) {
    const float* x = nullptr;
    const float* W = nullptr;
    const float* bias = nullptr;
    for (int i = 0; i < n_in; i++) {
        if (in_sizes[i] == 33554432) x = (const float*)d_in[i];       // 32*512*128*16
        else if (in_sizes[i] == 8388608) W = (const float*)d_in[i];   // 16*512*512*2
        else if (in_sizes[i] == 8192) bias = (const float*)d_in[i];   // 16*512
    }
    float* out = (float*)d_out;

    split_fused_kernel<<<12288, 256>>>(x, W);

    cudaFuncSetAttribute(gemm_kernel, cudaFuncAttributeMaxDynamicSharedMemorySize, SMEM_BYTES);
    gemm_kernel<<<dim3(NODES, 8, 32), 256, SMEM_BYTES>>>(bias, out);
}

// round 15
// speedup vs baseline: 1.2972x; 1.2972x over previous
#include <cuda_runtime.h>
#include <cuda_fp16.h>
#include <cstdint>

// Problem:
// x: [32, 512, 128, 16] f32, W: [16, 512, 512, 2] f32, bias: [16, 512] f32
// out: [32, 512, 128, 32] f32
// Per node n: 16 independent GEMMs A[4096, 512] * B[512, 1024] + bias.
//
// CHAMPION CONFIG (R13, 286.4us, rel_err 3.59e-4):
// fp16 single-GEMM + fp16 intermediate y. GEMM sits at the legacy mma.sync
// issue floor (tcgen05 unavailable: harness PTX targets sm_103 without 'a').
// Pipeline: fused split prepass (split_x = direct register transpose),
// HMMA GEMM -> y[n][m][j] fp16, repack (node-gather + bias, smem transpose,
// uint4 loads). All three components measured at/near their floors:
// split 40us (~traffic floor), gemm ~190us (issue wall), repack ~57us.
// R14's in-kernel fused repack tail regressed (regs 128, mainloop slowed);
// reverted.

#define M_TOTAL    4096   // 32*128
#define K_DIM      512
#define N_PER_NODE 1024
#define NODES      16

__device__ __half g_xh[(size_t)NODES * M_TOTAL * K_DIM];      // [n][m][c] 64MB
__device__ __half g_wh[(size_t)NODES * N_PER_NODE * K_DIM];   // [n][j][c] 16MB
__device__ __half g_yh[(size_t)NODES * M_TOTAL * N_PER_NODE]; // [n][m][j] 134MB

static __device__ __forceinline__ uint32_t smem_u32(const void* p) {
    uint32_t a;
    asm("{ .reg .u64 t; cvta.to.shared.u64 t, %1; cvt.u32.u64 %0, t; }"
        : "=r"(a) : "l"(p));
    return a;
}

static __device__ __forceinline__ void cp_async16(uint32_t saddr, const void* gaddr) {
    asm volatile("cp.async.cg.shared.global [%0], [%1], 16;"
                 :: "r"(saddr), "l"(gaddr) : "memory");
}
static __device__ __forceinline__ void cp_commit() {
    asm volatile("cp.async.commit_group;" ::: "memory");
}
template <int N>
static __device__ __forceinline__ void cp_wait() {
    asm volatile("cp.async.wait_group %0;" :: "n"(N) : "memory");
}

static __device__ __forceinline__ void ldsm_x4(uint32_t* r, uint32_t addr) {
    asm volatile("ldmatrix.sync.aligned.m8n8.x4.shared.b16 {%0,%1,%2,%3}, [%4];"
                 : "=r"(r[0]), "=r"(r[1]), "=r"(r[2]), "=r"(r[3]) : "r"(addr));
}

static __device__ __forceinline__ void mma_f16(float* c, const uint32_t* a,
                                               uint32_t b0, uint32_t b1) {
    asm volatile(
        "mma.sync.aligned.m16n8k16.row.col.f32.f16.f16.f32 "
        "{%0,%1,%2,%3}, {%4,%5,%6,%7}, {%8,%9}, {%0,%1,%2,%3};"
        : "+f"(c[0]), "+f"(c[1]), "+f"(c[2]), "+f"(c[3])
        : "r"(a[0]), "r"(a[1]), "r"(a[2]), "r"(a[3]), "r"(b0), "r"(b1));
}

static __device__ __forceinline__ void stcs_f4(float* p, float4 v) {
    asm volatile("st.global.cs.v4.f32 [%0], {%1,%2,%3,%4};"
                 :: "l"(p), "f"(v.x), "f"(v.y), "f"(v.z), "f"(v.w) : "memory");
}

// ---------------------------------------------------------------------------
// Fused prepass: blocks [0, 4096) do split_x, [4096, 12288) do split_w.
// split_x: DIRECT register transpose, no smem: each thread owns one output
//   row segment (n, m=b*128+f0+fl, c in [c0+half*32, +32)). Per c, even/odd
//   half-warps read contiguous 64B runs of x; 32 independent LDGs (MLP=32),
//   then one 64B contiguous fp16 store. No barrier.
// split_w: 32x32 smem transpose tile.
// ---------------------------------------------------------------------------
__global__ __launch_bounds__(256) void split_fused_kernel(const float* __restrict__ x,
                                                          const float* __restrict__ W) {
    __shared__ float sw[32][33];   // used by split_w branch only
    const int tid = threadIdx.x;
    const int bid = blockIdx.x;

    if (bid < 4096) {
        // ---- split_x (direct) ----
        const int c0 = (bid & 7) * 64;
        const int f0 = ((bid >> 3) & 15) * 8;
        const int b  = bid >> 7;

        const int row  = tid >> 1;     // 0..127  (fn index)
        const int half = tid & 1;
        const int fl = row >> 4;       // 0..7
        const int n  = row & 15;
        const int cbase = c0 + half * 32;

        // src address for c = cbase+cc: x[b][c][f0+fl][n]
        const float* src = x + (size_t)b * 1048576 + (size_t)cbase * 2048
                         + (size_t)(f0 + fl) * 16 + n;

        float v[32];
        #pragma unroll
        for (int cc = 0; cc < 32; cc++)
            v[cc] = src[(size_t)cc * 2048];

        __align__(16) __half hv[32];
        #pragma unroll
        for (int cc = 0; cc < 32; cc++)
            hv[cc] = __float2half_rn(v[cc]);

        const int m = b * 128 + f0 + fl;
        const size_t obase = (size_t)n * ((size_t)M_TOTAL * K_DIM)
                           + (size_t)m * K_DIM + cbase;
        uint4* ph = reinterpret_cast<uint4*>(&g_xh[obase]);
        #pragma unroll
        for (int q = 0; q < 4; q++)
            ph[q] = reinterpret_cast<uint4*>(hv)[q];
    } else {
        // ---- split_w ----
        const int wb = bid - 4096;
        const int j0 = (wb & 31) * 32;
        const int c0 = ((wb >> 5) & 15) * 32;
        const int n  = wb >> 9;

        #pragma unroll
        for (int it = 0; it < 4; it++) {
            int idx = tid + it * 256;
            int i = idx >> 5;   // c local
            int jj = idx & 31;  // j local
            sw[i][jj] = W[(size_t)n * 524288 + (size_t)(c0 + i) * 1024 + j0 + jj];
        }
        __syncthreads();
        #pragma unroll
        for (int it = 0; it < 4; it++) {
            int idx = tid + it * 256;
            int jj = idx >> 5;  // j local
            int i = idx & 31;   // c local
            size_t o = (size_t)n * 524288 + (size_t)(j0 + jj) * 512 + c0 + i;
            g_wh[o] = __float2half_rn(sw[i][jj]);
        }
    }
}

// ---------------------------------------------------------------------------
// GEMM (champion R9 config — at the mma.sync issue floor): one CTA per
// (node, jt, mt): 128x128 tile, K=512 in 8 chunks of 64, 3-stage cp.async
// pipeline, 8 warps 4(m) x 2(j). Output: dense fp16 y[n][m][j].
// ---------------------------------------------------------------------------
#define KC       64
#define CHUNKS   8
#define STAGE_BYTES 16384               // 128 rows * 128B
#define SMEM_BYTES  (6 * STAGE_BYTES)   // 3 stages x (A+B) = 96KB

__global__ __launch_bounds__(256, 2) void gemm_kernel() {
    extern __shared__ char smem[];
    const uint32_t sbase = smem_u32(smem);
    const int tid = threadIdx.x;
    const int wid = tid >> 5;
    const int lane = tid & 31;

    const int node = blockIdx.x;
    const int jt = blockIdx.y;    // 0..7
    const int mt = blockIdx.z;    // 0..31

    const __half* abase = g_xh + (size_t)node * ((size_t)M_TOTAL * K_DIM)
                        + (size_t)mt * 128 * K_DIM;
    const __half* bbase = g_wh + (size_t)node * ((size_t)N_PER_NODE * K_DIM)
                        + (size_t)jt * 128 * K_DIM;

    const int ld_row = tid >> 3;
    const int ld_col = tid & 7;

    auto issue_chunk = [&](int chunk, int stage) {
        const __half* ap = abase + chunk * KC;
        const __half* bp = bbase + chunk * KC;
        uint32_t sa = sbase + stage * STAGE_BYTES;
        uint32_t sb = sbase + 3 * STAGE_BYTES + stage * STAGE_BYTES;
        #pragma unroll
        for (int p = 0; p < 4; p++) {
            int row = ld_row + p * 32;
            uint32_t soff = (uint32_t)row * 128 + (uint32_t)((ld_col ^ (row & 7)) << 4);
            cp_async16(sa + soff, ap + (size_t)row * K_DIM + ld_col * 8);
            cp_async16(sb + soff, bp + (size_t)row * K_DIM + ld_col * 8);
        }
    };

    const int wm = (wid & 3) * 32;
    const int wj = (wid >> 2) * 64;

    const int a_row0 = wm + (lane & 7) + (lane & 8);          // + mt2*16
    const int a_csel = (lane >> 4) & 1;
    const int b_row0 = wj + (lane & 7) + ((lane & 16) >> 1);  // + nt*16
    const int b_csel = (lane >> 3) & 1;

    float acc[2][8][4];
    #pragma unroll
    for (int i = 0; i < 2; i++)
        #pragma unroll
        for (int j = 0; j < 8; j++)
            #pragma unroll
            for (int k = 0; k < 4; k++) acc[i][j][k] = 0.f;

    issue_chunk(0, 0); cp_commit();
    issue_chunk(1, 1); cp_commit();

    int stage = 0;
    for (int i = 0; i < CHUNKS; i++) {
        cp_wait<1>();
        __syncthreads();

        uint32_t sa = sbase + stage * STAGE_BYTES;
        uint32_t sb = sbase + 3 * STAGE_BYTES + stage * STAGE_BYTES;

        #pragma unroll
        for (int kk = 0; kk < 4; kk++) {
            uint32_t afrag[2][4];
            uint32_t bfrag[4][4];
            #pragma unroll
            for (int mt2 = 0; mt2 < 2; mt2++) {
                int row = a_row0 + mt2 * 16;
                uint32_t addr = sa + (uint32_t)row * 128
                              + (uint32_t)(((2 * kk + a_csel) ^ (row & 7)) << 4);
                ldsm_x4(afrag[mt2], addr);
            }
            #pragma unroll
            for (int nt = 0; nt < 4; nt++) {
                int row = b_row0 + nt * 16;
                uint32_t addr = sb + (uint32_t)row * 128
                              + (uint32_t)(((2 * kk + b_csel) ^ (row & 7)) << 4);
                ldsm_x4(bfrag[nt], addr);
            }
            #pragma unroll
            for (int mt2 = 0; mt2 < 2; mt2++)
                #pragma unroll
                for (int n8 = 0; n8 < 8; n8++)
                    mma_f16(acc[mt2][n8], afrag[mt2],
                            bfrag[n8 >> 1][(n8 & 1) * 2], bfrag[n8 >> 1][(n8 & 1) * 2 + 1]);
        }

        __syncthreads();
        if (i + 2 < CHUNKS) issue_chunk(i + 2, (stage + 2) % 3);
        cp_commit();
        stage = (stage + 1) % 3;
    }

    // Epilogue: dense fp16 write to y[node][m][j], coalesced half2 stores.
    __half* ybase = g_yh + ((size_t)node * M_TOTAL + (size_t)mt * 128) * N_PER_NODE
                  + jt * 128;
    #pragma unroll
    for (int mt2 = 0; mt2 < 2; mt2++) {
        const int ml = wm + mt2 * 16 + (lane >> 2);
        __half* r0 = ybase + (size_t)ml * N_PER_NODE;
        __half* r1 = ybase + (size_t)(ml + 8) * N_PER_NODE;
        #pragma unroll
        for (int n8 = 0; n8 < 8; n8++) {
            int j = wj + n8 * 8 + (lane & 3) * 2;
            *reinterpret_cast<__half2*>(r0 + j) =
                __floats2half2_rn(acc[mt2][n8][0], acc[mt2][n8][1]);
            *reinterpret_cast<__half2*>(r1 + j) =
                __floats2half2_rn(acc[mt2][n8][2], acc[mt2][n8][3]);
        }
    }
}

// ---------------------------------------------------------------------------
// Repack (champion R12): out[b][o][f][n*2+k] = y[n][b*128+f][o*2+k] + bias.
// smem s[f*594 + j*18 + n] (PF=594 == 2 mod 32). Phase 1: uint4 y loads
// (4 LDG/thread, STS 2-way worst case). Phase 2: LDS.64 conflict-free,
// smem-staged bias, evict-first float4 out stores. grid (32, 8, 32).
// ---------------------------------------------------------------------------
#define RP_PF 594   // f-stride in floats (even, == 2 mod 32)

__global__ __launch_bounds__(256) void repack_kernel(const float* __restrict__ bias,
                                                     float* __restrict__ out) {
    __shared__ float s[15 * RP_PF + 31 * 18 + 16];  // ~37.2KB
    __shared__ float s_bias[16 * 16];               // [ol][n]
    const int o0 = blockIdx.x * 16;
    const int j0 = o0 * 2;
    const int f0 = blockIdx.y * 16;
    const int b  = blockIdx.z;
    const int tid = threadIdx.x;

    const size_t ynode = (size_t)M_TOTAL * N_PER_NODE;
    const __half* ybase = g_yh + ((size_t)b * 128 + f0) * N_PER_NODE + j0;

    {
        int ol = tid >> 4;
        int n  = tid & 15;
        s_bias[ol * 16 + n] = bias[n * 512 + o0 + ol];
    }

    // Phase 1: 16n x 16f x 4jo uint4 loads (8 j-halves each), 4 per thread.
    #pragma unroll
    for (int p = 0; p < 4; p++) {
        int idx = p * 256 + tid;      // 0..1023
        int jo = idx & 3;             // j = 8*jo .. 8*jo+7
        int f  = (idx >> 2) & 15;
        int n  = (idx >> 6) & 15;
        uint4 raw = *reinterpret_cast<const uint4*>(
            ybase + n * ynode + (size_t)f * N_PER_NODE + 8 * jo);
        float2 v01 = __half22float2(*reinterpret_cast<__half2*>(&raw.x));
        float2 v23 = __half22float2(*reinterpret_cast<__half2*>(&raw.y));
        float2 v45 = __half22float2(*reinterpret_cast<__half2*>(&raw.z));
        float2 v67 = __half22float2(*reinterpret_cast<__half2*>(&raw.w));
        float* sp = &s[f * RP_PF + (8 * jo) * 18 + n];
        sp[0]   = v01.x;
        sp[18]  = v01.y;
        sp[36]  = v23.x;
        sp[54]  = v23.y;
        sp[72]  = v45.x;
        sp[90]  = v45.y;
        sp[108] = v67.x;
        sp[126] = v67.y;
    }
    __syncthreads();

    // Phase 2: per float4 out chunk: 2 LDS.64 + smem bias, evict-first store.
    #pragma unroll
    for (int p = 0; p < 8; p++) {
        int idx = p * 256 + tid;      // 0..2047
        int ol = idx >> 7;            // 0..15
        int f  = (idx >> 3) & 15;
        int g  = idx & 7;
        int n0 = 2 * g;
        int jl = 2 * ol;
        float2 A = *reinterpret_cast<float2*>(&s[f * RP_PF + jl * 18 + n0]);
        float2 B = *reinterpret_cast<float2*>(&s[f * RP_PF + (jl + 1) * 18 + n0]);
        float b0 = s_bias[ol * 16 + n0];
        float b1 = s_bias[ol * 16 + n0 + 1];
        float4 v;
        v.x = A.x + b0;
        v.y = B.x + b0;
        v.z = A.y + b1;
        v.w = B.y + b1;
        size_t oaddr = (size_t)b * 2097152 + (size_t)(o0 + ol) * 4096
                     + (size_t)(f0 + f) * 32 + g * 4;
        stcs_f4(out + oaddr, v);
    }
}

// ---------------------------------------------------------------------------
extern "C" void kernel_launch(void* const* d_in, const int* in_sizes, int n_in,
                              void* d_out, int out_size) {
    const float* x = nullptr;
    const float* W = nullptr;
    const float* bias = nullptr;
    for (int i = 0; i < n_in; i++) {
        if (in_sizes[i] == 33554432) x = (const float*)d_in[i];       // 32*512*128*16
        else if (in_sizes[i] == 8388608) W = (const float*)d_in[i];   // 16*512*512*2
        else if (in_sizes[i] == 8192) bias = (const float*)d_in[i];   // 16*512
    }
    float* out = (float*)d_out;

    split_fused_kernel<<<12288, 256>>>(x, W);

    cudaFuncSetAttribute(gemm_kernel, cudaFuncAttributeMaxDynamicSharedMemorySize, SMEM_BYTES);
    gemm_kernel<<<dim3(NODES, 8, 32), 256, SMEM_BYTES>>>();

    repack_kernel<<<dim3(32, 8, 32), 256>>>(bias, out);
}